// round 1
// baseline (speedup 1.0000x reference)
#include <cuda_runtime.h>
#include <cstdint>

#define BB   32
#define TT   336
#define NH   100
#define NM   150
#define FH   8
#define FM   16
#define HG   64
#define HL   64
#define FUT  24

// Scratch: GNN output in [n][t][b][hg] layout (275 MB), so the LSTM block for
// node n streams contiguous [b][hg] tiles per timestep.
__device__ float g_x[(size_t)NH * TT * BB * HG];

// ---------------------------------------------------------------------------
// Kernel A: hetero GraphConv for one graph (b,t) per block.
// out = leaky_relu(0.5*(agg_h@Wrel_h^T + b_rel_h + xh@Wroot_h^T
//                       + agg_m@Wrel_m^T + b_rel_m + xh@Wroot_m^T))
// The 0.5 is folded into the weights/biases at SMEM load time.
// ---------------------------------------------------------------------------
__global__ void __launch_bounds__(256) gnn_kernel(
    const float* __restrict__ xm_all, const float* __restrict__ xh_all,
    const int* __restrict__ eh, const int* __restrict__ em,
    const float* __restrict__ Wrel_m, const float* __restrict__ brel_m,
    const float* __restrict__ Wroot_m,
    const float* __restrict__ Wrel_h, const float* __restrict__ brel_h,
    const float* __restrict__ Wroot_h,
    int Eh, int Em)
{
    __shared__ float sxh[NH * FH];    // hydro node feats
    __shared__ float sxm[NM * FM];    // meteo node feats
    __shared__ float sah[NH * FH];    // hydro aggregate
    __shared__ float sam[NH * FM];    // meteo aggregate
    __shared__ float swh[HG * FH];    // 0.5*W_rel_h
    __shared__ float swm[HG * FM];    // 0.5*W_rel_m
    __shared__ float swr[HG * FH];    // 0.5*(W_root_h + W_root_m)
    __shared__ float sb[HG];          // 0.5*(b_rel_h + b_rel_m)

    const int g = blockIdx.x;
    const int t = g % TT;
    const int b = g / TT;
    const int tid = threadIdx.x;

    const float* xh = xh_all + (size_t)g * NH * FH;
    const float* xm = xm_all + (size_t)g * NM * FM;

    for (int i = tid; i < NH * FH; i += 256) { sxh[i] = xh[i]; sah[i] = 0.f; }
    for (int i = tid; i < NM * FM; i += 256) sxm[i] = xm[i];
    for (int i = tid; i < NH * FM; i += 256) sam[i] = 0.f;
    for (int i = tid; i < HG * FH; i += 256) {
        swh[i] = 0.5f * Wrel_h[i];
        swr[i] = 0.5f * (Wroot_h[i] + Wroot_m[i]);
    }
    for (int i = tid; i < HG * FM; i += 256) swm[i] = 0.5f * Wrel_m[i];
    for (int i = tid; i < HG;      i += 256) sb[i]  = 0.5f * (brel_h[i] + brel_m[i]);
    __syncthreads();

    // scatter-add aggregation (shared-memory atomics)
    for (int e = tid; e < Eh; e += 256) {
        int s  = eh[e];
        int tg = eh[Eh + e];
        #pragma unroll
        for (int f = 0; f < FH; f++)
            atomicAdd(&sah[tg * FH + f], sxh[s * FH + f]);
    }
    for (int e = tid; e < Em; e += 256) {
        int s  = em[e];
        int tg = em[Em + e];
        #pragma unroll
        for (int f = 0; f < FM; f++)
            atomicAdd(&sam[tg * FM + f], sxm[s * FM + f]);
    }
    __syncthreads();

    // per-node linear: out[n][j], n<NH, j<HG
    for (int idx = tid; idx < NH * HG; idx += 256) {
        int n = idx / HG;
        int j = idx % HG;
        float acc = sb[j];
        #pragma unroll
        for (int k = 0; k < FH; k++)
            acc += sah[n * FH + k] * swh[j * FH + k]
                 + sxh[n * FH + k] * swr[j * FH + k];
        #pragma unroll
        for (int k = 0; k < FM; k++)
            acc += sam[n * FM + k] * swm[j * FM + k];
        float v = acc > 0.f ? acc : 0.01f * acc;
        g_x[(((size_t)n * TT + t) * BB + b) * HG + j] = v;
    }
}

// ---------------------------------------------------------------------------
// Kernel B: per-node LSTM. One block per node (100 blocks), 256 threads.
// Weights transposed to [k][j] in SMEM and kept resident over all T steps.
// Thread (tm=tid/32, tn=tid%32) owns batches b=4*tm..+3 and hidden units
// u={2*tn, 2*tn+1}; its GEMM N-footprint is {g*64 + 2*tn + du} for all 4
// gates, so the cell update is fully thread-local (c lives in registers).
// ---------------------------------------------------------------------------
#define OW_IH 0
#define OW_HH 16384
#define OX    32768               // [k][b], stride 33
#define OH    (32768 + 64*33)     // [k][b], stride 33
#define OBIAS (OH + 64*33)        // 256
#define OWL   (OBIAS + 256)       // 24*64
#define OBL   (OWL + 24*64)       // 24
#define SMEM_FLOATS (OBL + 32)
#define SMEM_BYTES  (SMEM_FLOATS * 4)

__device__ __forceinline__ float sigm(float x) {
    return 1.0f / (1.0f + __expf(-x));
}
__device__ __forceinline__ float tanh_fast(float x) {
    float xc = fminf(fmaxf(x, -15.f), 15.f);
    float e = __expf(2.0f * xc);
    return (e - 1.0f) / (e + 1.0f);
}

__global__ void __launch_bounds__(256) lstm_kernel(
    const float* __restrict__ W_ih, const float* __restrict__ W_hh,
    const float* __restrict__ b_ih, const float* __restrict__ b_hh,
    const float* __restrict__ W_lin, const float* __restrict__ b_lin,
    float* __restrict__ out)
{
    extern __shared__ float sm[];
    float* sWih  = sm + OW_IH;   // [k][j] stride 256
    float* sWhh  = sm + OW_HH;   // [k][j] stride 256
    float* sx    = sm + OX;      // [k][b] stride 33
    float* sh    = sm + OH;      // [k][b] stride 33
    float* sbias = sm + OBIAS;   // 256
    float* sWlin = sm + OWL;     // [f][u]
    float* sblin = sm + OBL;

    const int n   = blockIdx.x;
    const int tid = threadIdx.x;

    // load per-node weights, transposed
    const float* wih = W_ih + (size_t)n * 256 * 64;
    const float* whh = W_hh + (size_t)n * 256 * 64;
    for (int i = tid; i < 16384; i += 256) {
        int j = i >> 6, k = i & 63;
        sWih[k * 256 + j] = wih[i];
        sWhh[k * 256 + j] = whh[i];
    }
    sbias[tid] = b_ih[n * 256 + tid] + b_hh[n * 256 + tid];
    for (int i = tid; i < FUT * HL; i += 256) sWlin[i] = W_lin[i];
    if (tid < FUT) sblin[tid] = b_lin[tid];
    for (int i = tid; i < 64 * 33; i += 256) sh[i] = 0.f;

    const int tm = tid >> 5;   // 0..7  -> batch base 4*tm
    const int tn = tid & 31;   // 0..31 -> unit base 2*tn

    float c[4][2];
    #pragma unroll
    for (int mi = 0; mi < 4; mi++) { c[mi][0] = 0.f; c[mi][1] = 0.f; }

    const float* xptr = g_x + (size_t)n * TT * BB * HG;  // [t][b][hg]

    const int sb_b = tid >> 3;          // staging: batch
    const int sb_k = (tid & 7) << 3;    // staging: k base (8 floats)

    for (int t = 0; t < TT; t++) {
        // stage x_t transposed into sx[k][b]
        const float* xt = xptr + (size_t)t * BB * HG;
        float4 v0 = *(const float4*)&xt[sb_b * HG + sb_k];
        float4 v1 = *(const float4*)&xt[sb_b * HG + sb_k + 4];
        sx[(sb_k + 0) * 33 + sb_b] = v0.x;
        sx[(sb_k + 1) * 33 + sb_b] = v0.y;
        sx[(sb_k + 2) * 33 + sb_b] = v0.z;
        sx[(sb_k + 3) * 33 + sb_b] = v0.w;
        sx[(sb_k + 4) * 33 + sb_b] = v1.x;
        sx[(sb_k + 5) * 33 + sb_b] = v1.y;
        sx[(sb_k + 6) * 33 + sb_b] = v1.z;
        sx[(sb_k + 7) * 33 + sb_b] = v1.w;
        __syncthreads();   // sx staged; previous-step h writes visible

        float acc[4][8];
        #pragma unroll
        for (int mi = 0; mi < 4; mi++)
            #pragma unroll
            for (int gg = 0; gg < 4; gg++) {
                acc[mi][gg * 2 + 0] = sbias[gg * 64 + 2 * tn + 0];
                acc[mi][gg * 2 + 1] = sbias[gg * 64 + 2 * tn + 1];
            }

        #pragma unroll 4
        for (int k = 0; k < 64; k++) {
            float xv[4], hv[4];
            #pragma unroll
            for (int mi = 0; mi < 4; mi++) xv[mi] = sx[k * 33 + 4 * tm + mi];
            #pragma unroll
            for (int gg = 0; gg < 4; gg++) {
                float2 w = *(const float2*)&sWih[k * 256 + gg * 64 + 2 * tn];
                #pragma unroll
                for (int mi = 0; mi < 4; mi++) {
                    acc[mi][gg * 2 + 0] += xv[mi] * w.x;
                    acc[mi][gg * 2 + 1] += xv[mi] * w.y;
                }
            }
            #pragma unroll
            for (int mi = 0; mi < 4; mi++) hv[mi] = sh[k * 33 + 4 * tm + mi];
            #pragma unroll
            for (int gg = 0; gg < 4; gg++) {
                float2 w = *(const float2*)&sWhh[k * 256 + gg * 64 + 2 * tn];
                #pragma unroll
                for (int mi = 0; mi < 4; mi++) {
                    acc[mi][gg * 2 + 0] += hv[mi] * w.x;
                    acc[mi][gg * 2 + 1] += hv[mi] * w.y;
                }
            }
        }
        __syncthreads();   // all GEMM reads of sh done; safe to overwrite

        // local cell update (gate order: i, f, g, o)
        #pragma unroll
        for (int mi = 0; mi < 4; mi++) {
            #pragma unroll
            for (int du = 0; du < 2; du++) {
                float ig = sigm(acc[mi][0 * 2 + du]);
                float fg = sigm(acc[mi][1 * 2 + du]);
                float gg = tanh_fast(acc[mi][2 * 2 + du]);
                float og = sigm(acc[mi][3 * 2 + du]);
                float cc = fg * c[mi][du] + ig * gg;
                c[mi][du] = cc;
                sh[(2 * tn + du) * 33 + (4 * tm + mi)] = og * tanh_fast(cc);
            }
        }
        // no sync here: next loop's staging touches only sx; the sync after
        // staging orders these sh writes before the next GEMM's reads.
    }
    __syncthreads();

    // final head: pred[b][n][f] = leaky(h_last[b] . W_lin[f] + b_lin[f])
    for (int idx = tid; idx < BB * FUT; idx += 256) {
        int b = idx / FUT;
        int f = idx % FUT;
        float acc = sblin[f];
        #pragma unroll
        for (int u = 0; u < HL; u++)
            acc += sh[u * 33 + b] * sWlin[f * HL + u];
        float v = acc > 0.f ? acc : 0.01f * acc;
        out[((size_t)b * NH + n) * FUT + f] = v;
    }
}

// ---------------------------------------------------------------------------
extern "C" void kernel_launch(void* const* d_in, const int* in_sizes, int n_in,
                              void* d_out, int out_size)
{
    const float* data_meteo = (const float*)d_in[0];
    const float* data_hydro = (const float*)d_in[1];
    const int*   eh         = (const int*)  d_in[2];
    const int*   em         = (const int*)  d_in[3];
    const float* W_rel_m    = (const float*)d_in[4];
    const float* b_rel_m    = (const float*)d_in[5];
    const float* W_root_m   = (const float*)d_in[6];
    const float* W_rel_h    = (const float*)d_in[7];
    const float* b_rel_h    = (const float*)d_in[8];
    const float* W_root_h   = (const float*)d_in[9];
    const float* W_ih       = (const float*)d_in[10];
    const float* W_hh       = (const float*)d_in[11];
    const float* b_ih       = (const float*)d_in[12];
    const float* b_hh       = (const float*)d_in[13];
    const float* W_lin      = (const float*)d_in[14];
    const float* b_lin      = (const float*)d_in[15];

    const int Eh = in_sizes[2] / 2;
    const int Em = in_sizes[3] / 2;

    gnn_kernel<<<BB * TT, 256>>>(data_meteo, data_hydro, eh, em,
                                 W_rel_m, b_rel_m, W_root_m,
                                 W_rel_h, b_rel_h, W_root_h,
                                 Eh, Em);

    cudaFuncSetAttribute(lstm_kernel,
                         cudaFuncAttributeMaxDynamicSharedMemorySize,
                         SMEM_BYTES);
    lstm_kernel<<<NH, 256, SMEM_BYTES>>>(W_ih, W_hh, b_ih, b_hh,
                                         W_lin, b_lin, (float*)d_out);
}

// round 2
// speedup vs baseline: 1.2063x; 1.2063x over previous
#include <cuda_runtime.h>
#include <cstdint>

#define BB   32
#define TT   336
#define NH   100
#define NM   150
#define FH   8
#define FM   16
#define HG   64
#define HL   64
#define FUT  24
#define TC   16   // timesteps per precompute block

// GNN output x: [n][t][b][hg]
__device__ float g_x[(size_t)NH * TT * BB * HG];
// Precomputed x-gates (+bias): [n][t][b][256]
__device__ float g_gates[(size_t)NH * TT * BB * 256];

// ---------------------------------------------------------------------------
// Kernel A: hetero GraphConv, one graph (b,t) per block.
// ---------------------------------------------------------------------------
__global__ void __launch_bounds__(256) gnn_kernel(
    const float* __restrict__ xm_all, const float* __restrict__ xh_all,
    const int* __restrict__ eh, const int* __restrict__ em,
    const float* __restrict__ Wrel_m, const float* __restrict__ brel_m,
    const float* __restrict__ Wroot_m,
    const float* __restrict__ Wrel_h, const float* __restrict__ brel_h,
    const float* __restrict__ Wroot_h,
    int Eh, int Em)
{
    __shared__ float sxh[NH * FH];
    __shared__ float sxm[NM * FM];
    __shared__ float sah[NH * FH];
    __shared__ float sam[NH * FM];
    __shared__ float swh[HG * FH];
    __shared__ float swm[HG * FM];
    __shared__ float swr[HG * FH];
    __shared__ float sb[HG];

    const int g = blockIdx.x;
    const int t = g % TT;
    const int b = g / TT;
    const int tid = threadIdx.x;

    const float* xh = xh_all + (size_t)g * NH * FH;
    const float* xm = xm_all + (size_t)g * NM * FM;

    for (int i = tid; i < NH * FH; i += 256) { sxh[i] = xh[i]; sah[i] = 0.f; }
    for (int i = tid; i < NM * FM; i += 256) sxm[i] = xm[i];
    for (int i = tid; i < NH * FM; i += 256) sam[i] = 0.f;
    for (int i = tid; i < HG * FH; i += 256) {
        swh[i] = 0.5f * Wrel_h[i];
        swr[i] = 0.5f * (Wroot_h[i] + Wroot_m[i]);
    }
    for (int i = tid; i < HG * FM; i += 256) swm[i] = 0.5f * Wrel_m[i];
    for (int i = tid; i < HG;      i += 256) sb[i]  = 0.5f * (brel_h[i] + brel_m[i]);
    __syncthreads();

    for (int e = tid; e < Eh; e += 256) {
        int s  = eh[e];
        int tg = eh[Eh + e];
        #pragma unroll
        for (int f = 0; f < FH; f++)
            atomicAdd(&sah[tg * FH + f], sxh[s * FH + f]);
    }
    for (int e = tid; e < Em; e += 256) {
        int s  = em[e];
        int tg = em[Em + e];
        #pragma unroll
        for (int f = 0; f < FM; f++)
            atomicAdd(&sam[tg * FM + f], sxm[s * FM + f]);
    }
    __syncthreads();

    for (int idx = tid; idx < NH * HG; idx += 256) {
        int n = idx / HG;
        int j = idx % HG;
        float acc = sb[j];
        #pragma unroll
        for (int k = 0; k < FH; k++)
            acc += sah[n * FH + k] * swh[j * FH + k]
                 + sxh[n * FH + k] * swr[j * FH + k];
        #pragma unroll
        for (int k = 0; k < FM; k++)
            acc += sam[n * FM + k] * swm[j * FM + k];
        float v = acc > 0.f ? acc : 0.01f * acc;
        g_x[(((size_t)n * TT + t) * BB + b) * HG + j] = v;
    }
}

// ---------------------------------------------------------------------------
// Kernel B: x-gate precompute. grid (NH, TT/TC), 256 threads, 3 blocks/SM.
// gates[n][t][b][j] = x[n][t][b][:]@W_ih[n]^T[:,j] + b_ih[n][j] + b_hh[n][j]
// ---------------------------------------------------------------------------
#define XG_SW 0                 // [k][j] stride 256  (16384 floats)
#define XG_SB 16384             // 256
#define XG_SX (16384 + 256)     // [k][b] stride 33   (2112 floats)
#define XG_FLOATS (XG_SX + 64*33)
#define XG_BYTES  (XG_FLOATS * 4)

__global__ void __launch_bounds__(256, 3) xgemm_kernel(
    const float* __restrict__ W_ih,
    const float* __restrict__ b_ih, const float* __restrict__ b_hh)
{
    extern __shared__ float sm[];
    float* sW = sm + XG_SW;
    float* sb = sm + XG_SB;
    float* sx = sm + XG_SX;

    const int n   = blockIdx.x;
    const int t0  = blockIdx.y * TC;
    const int tid = threadIdx.x;

    const float* w = W_ih + (size_t)n * 256 * 64;
    for (int i = tid; i < 16384; i += 256) {
        int j = i >> 6, k = i & 63;
        sW[k * 256 + j] = w[i];
    }
    sb[tid] = b_ih[n * 256 + tid] + b_hh[n * 256 + tid];

    const int tm = tid >> 5;          // batch group 0..7
    const int tn = tid & 31;          // unit pair 0..31
    const int sb_b = tid >> 3;        // staging batch 0..31
    const int sb_k = (tid & 7) << 3;  // staging k base

    const float* xbase = g_x + ((size_t)n * TT + t0) * BB * HG;
    float* gbase = g_gates + ((size_t)n * TT + t0) * BB * 256;
    __syncthreads();

    for (int tt = 0; tt < TC; tt++) {
        const float* xt = xbase + (size_t)tt * BB * HG;
        float4 v0 = *(const float4*)&xt[sb_b * HG + sb_k];
        float4 v1 = *(const float4*)&xt[sb_b * HG + sb_k + 4];
        sx[(sb_k + 0) * 33 + sb_b] = v0.x;
        sx[(sb_k + 1) * 33 + sb_b] = v0.y;
        sx[(sb_k + 2) * 33 + sb_b] = v0.z;
        sx[(sb_k + 3) * 33 + sb_b] = v0.w;
        sx[(sb_k + 4) * 33 + sb_b] = v1.x;
        sx[(sb_k + 5) * 33 + sb_b] = v1.y;
        sx[(sb_k + 6) * 33 + sb_b] = v1.z;
        sx[(sb_k + 7) * 33 + sb_b] = v1.w;
        __syncthreads();

        float acc[4][8];
        #pragma unroll
        for (int mi = 0; mi < 4; mi++)
            #pragma unroll
            for (int gg = 0; gg < 4; gg++) {
                acc[mi][gg * 2 + 0] = sb[gg * 64 + 2 * tn + 0];
                acc[mi][gg * 2 + 1] = sb[gg * 64 + 2 * tn + 1];
            }

        #pragma unroll 4
        for (int k = 0; k < 64; k++) {
            float xv[4];
            #pragma unroll
            for (int mi = 0; mi < 4; mi++) xv[mi] = sx[k * 33 + 4 * tm + mi];
            #pragma unroll
            for (int gg = 0; gg < 4; gg++) {
                float2 wv = *(const float2*)&sW[k * 256 + gg * 64 + 2 * tn];
                #pragma unroll
                for (int mi = 0; mi < 4; mi++) {
                    acc[mi][gg * 2 + 0] += xv[mi] * wv.x;
                    acc[mi][gg * 2 + 1] += xv[mi] * wv.y;
                }
            }
        }

        float* gt = gbase + (size_t)tt * BB * 256;
        #pragma unroll
        for (int mi = 0; mi < 4; mi++)
            #pragma unroll
            for (int gg = 0; gg < 4; gg++) {
                float2 v; v.x = acc[mi][gg * 2]; v.y = acc[mi][gg * 2 + 1];
                *(float2*)&gt[(4 * tm + mi) * 256 + gg * 64 + 2 * tn] = v;
            }
        __syncthreads();   // sx reads done before next stage overwrites
    }
}

// ---------------------------------------------------------------------------
// Kernel C: recurrent LSTM, h-half only. One block per node, 256 threads.
// Double-buffered h (1 sync/step), x-gates prefetched from gmem one step ahead.
// ---------------------------------------------------------------------------
#define O_WHH 0
#define O_H   16384               // 2 buffers of [k][b] stride 33
#define HBUF  (64*33)
#define O_WL  (O_H + 2*HBUF)
#define O_BL  (O_WL + 24*64)
#define LS_FLOATS (O_BL + 32)
#define LS_BYTES  (LS_FLOATS * 4)

__device__ __forceinline__ float sigm(float x) {
    return 1.0f / (1.0f + __expf(-x));
}
__device__ __forceinline__ float tanh_fast(float x) {
    float xc = fminf(fmaxf(x, -15.f), 15.f);
    float e = __expf(2.0f * xc);
    return (e - 1.0f) / (e + 1.0f);
}

__global__ void __launch_bounds__(256) lstm_kernel(
    const float* __restrict__ W_hh,
    const float* __restrict__ W_lin, const float* __restrict__ b_lin,
    float* __restrict__ out)
{
    extern __shared__ float sm[];
    float* sWhh  = sm + O_WHH;   // [k][j] stride 256
    float* sh    = sm + O_H;     // 2 x [k][b] stride 33
    float* sWlin = sm + O_WL;
    float* sblin = sm + O_BL;

    const int n   = blockIdx.x;
    const int tid = threadIdx.x;

    const float* whh = W_hh + (size_t)n * 256 * 64;
    for (int i = tid; i < 16384; i += 256) {
        int j = i >> 6, k = i & 63;
        sWhh[k * 256 + j] = whh[i];
    }
    for (int i = tid; i < FUT * HL; i += 256) sWlin[i] = W_lin[i];
    if (tid < FUT) sblin[tid] = b_lin[tid];
    for (int i = tid; i < HBUF; i += 256) sh[i] = 0.f;   // h0 buffer

    const int tm = tid >> 5;   // batch base 4*tm
    const int tn = tid & 31;   // unit base 2*tn

    float c[4][2];
    #pragma unroll
    for (int mi = 0; mi < 4; mi++) { c[mi][0] = 0.f; c[mi][1] = 0.f; }

    const float* gptr = g_gates + (size_t)n * TT * BB * 256;

    // prefetch gates for t=0
    float gb[4][8];
    #pragma unroll
    for (int mi = 0; mi < 4; mi++)
        #pragma unroll
        for (int gg = 0; gg < 4; gg++) {
            float2 v = *(const float2*)&gptr[(4 * tm + mi) * 256 + gg * 64 + 2 * tn];
            gb[mi][gg * 2] = v.x; gb[mi][gg * 2 + 1] = v.y;
        }

    for (int t = 0; t < TT; t++) {
        float acc[4][8];
        #pragma unroll
        for (int mi = 0; mi < 4; mi++)
            #pragma unroll
            for (int q = 0; q < 8; q++) acc[mi][q] = gb[mi][q];

        // prefetch next step's gates (latency hidden under the k-loop)
        if (t + 1 < TT) {
            const float* gnx = gptr + (size_t)(t + 1) * BB * 256;
            #pragma unroll
            for (int mi = 0; mi < 4; mi++)
                #pragma unroll
                for (int gg = 0; gg < 4; gg++) {
                    float2 v = *(const float2*)&gnx[(4 * tm + mi) * 256 + gg * 64 + 2 * tn];
                    gb[mi][gg * 2] = v.x; gb[mi][gg * 2 + 1] = v.y;
                }
        }

        const float* hb = sh + (t & 1) * HBUF;        // read buffer
        float*       hw = sh + ((t + 1) & 1) * HBUF;  // write buffer
        __syncthreads();   // prev step's h writes (into hb) visible

        #pragma unroll 4
        for (int k = 0; k < 64; k++) {
            float hv[4];
            #pragma unroll
            for (int mi = 0; mi < 4; mi++) hv[mi] = hb[k * 33 + 4 * tm + mi];
            #pragma unroll
            for (int gg = 0; gg < 4; gg++) {
                float2 w = *(const float2*)&sWhh[k * 256 + gg * 64 + 2 * tn];
                #pragma unroll
                for (int mi = 0; mi < 4; mi++) {
                    acc[mi][gg * 2 + 0] += hv[mi] * w.x;
                    acc[mi][gg * 2 + 1] += hv[mi] * w.y;
                }
            }
        }

        // cell update (gate order i, f, g, o); write h into the other buffer
        #pragma unroll
        for (int mi = 0; mi < 4; mi++) {
            #pragma unroll
            for (int du = 0; du < 2; du++) {
                float ig = sigm(acc[mi][0 * 2 + du]);
                float fg = sigm(acc[mi][1 * 2 + du]);
                float gg = tanh_fast(acc[mi][2 * 2 + du]);
                float og = sigm(acc[mi][3 * 2 + du]);
                float cc = fg * c[mi][du] + ig * gg;
                c[mi][du] = cc;
                hw[(2 * tn + du) * 33 + (4 * tm + mi)] = og * tanh_fast(cc);
            }
        }
    }
    __syncthreads();

    // h_last lives in buffer (TT & 1) == 0
    float* hl = sh + ((TT) & 1) * HBUF;
    for (int idx = tid; idx < BB * FUT; idx += 256) {
        int b = idx / FUT;
        int f = idx % FUT;
        float acc = sblin[f];
        #pragma unroll
        for (int u = 0; u < HL; u++)
            acc += hl[u * 33 + b] * sWlin[f * HL + u];
        float v = acc > 0.f ? acc : 0.01f * acc;
        out[((size_t)b * NH + n) * FUT + f] = v;
    }
}

// ---------------------------------------------------------------------------
extern "C" void kernel_launch(void* const* d_in, const int* in_sizes, int n_in,
                              void* d_out, int out_size)
{
    const float* data_meteo = (const float*)d_in[0];
    const float* data_hydro = (const float*)d_in[1];
    const int*   eh         = (const int*)  d_in[2];
    const int*   em         = (const int*)  d_in[3];
    const float* W_rel_m    = (const float*)d_in[4];
    const float* b_rel_m    = (const float*)d_in[5];
    const float* W_root_m   = (const float*)d_in[6];
    const float* W_rel_h    = (const float*)d_in[7];
    const float* b_rel_h    = (const float*)d_in[8];
    const float* W_root_h   = (const float*)d_in[9];
    const float* W_ih       = (const float*)d_in[10];
    const float* W_hh       = (const float*)d_in[11];
    const float* b_ih       = (const float*)d_in[12];
    const float* b_hh       = (const float*)d_in[13];
    const float* W_lin      = (const float*)d_in[14];
    const float* b_lin      = (const float*)d_in[15];

    const int Eh = in_sizes[2] / 2;
    const int Em = in_sizes[3] / 2;

    gnn_kernel<<<BB * TT, 256>>>(data_meteo, data_hydro, eh, em,
                                 W_rel_m, b_rel_m, W_root_m,
                                 W_rel_h, b_rel_h, W_root_h,
                                 Eh, Em);

    cudaFuncSetAttribute(xgemm_kernel,
                         cudaFuncAttributeMaxDynamicSharedMemorySize, XG_BYTES);
    dim3 xg(NH, TT / TC);
    xgemm_kernel<<<xg, 256, XG_BYTES>>>(W_ih, b_ih, b_hh);

    cudaFuncSetAttribute(lstm_kernel,
                         cudaFuncAttributeMaxDynamicSharedMemorySize, LS_BYTES);
    lstm_kernel<<<NH, 256, LS_BYTES>>>(W_hh, W_lin, b_lin, (float*)d_out);
}